// round 9
// baseline (speedup 1.0000x reference)
#include <cuda_runtime.h>
#include <math.h>
#include <stdint.h>

#define Bn 8
#define Ln 8
#define Cn 64
#define Hn 56
#define Wn 56
#define HWn 3136
#define BCn (Bn*Cn)        // 512
#define BLn (Bn*Ln)        // 64
#define NTOT (BLn*Cn*HWn)  // 12,845,056
#define KWC 29             // compact kw count (Hermitian half)
#define NPOS (56*KWC)      // 1624 positions per slab
#define TILES 28           // k4t: 2 output rows per tile
#define NBLK (BLn*TILES)   // 1792 BN-partial slots

typedef unsigned long long u64;

__device__ __forceinline__ u64 ffma2(u64 a, u64 b, u64 c) {
    u64 d;
    asm("fma.rn.f32x2 %0, %1, %2, %3;" : "=l"(d) : "l"(a), "l"(b), "l"(c));
    return d;
}
__device__ __forceinline__ u64 pack2(float lo, float hi) {
    u64 d;
    asm("mov.b64 %0, {%1, %2};" : "=l"(d) : "f"(lo), "f"(hi));
    return d;
}
__device__ __forceinline__ float2 unpack2(u64 v) {
    float2 r;
    asm("mov.b64 {%0, %1}, %2;" : "=f"(r.x), "=f"(r.y) : "l"(v));
    return r;
}
__device__ __forceinline__ uint32_t f2tf32(float v) {
    uint32_t b;
    asm("cvt.rna.tf32.f32 %0, %1;" : "=r"(b) : "f"(v));
    return b;
}
__device__ __forceinline__ void mma_tf32(float* d, const uint32_t* a, const uint32_t* b) {
    asm volatile(
        "mma.sync.aligned.m16n8k8.row.col.f32.tf32.tf32.f32 "
        "{%0,%1,%2,%3}, {%4,%5,%6,%7}, {%8,%9}, {%0,%1,%2,%3};\n"
        : "+f"(d[0]), "+f"(d[1]), "+f"(d[2]), "+f"(d[3])
        : "r"(a[0]), "r"(a[1]), "r"(a[2]), "r"(a[3]), "r"(b[0]), "r"(b[1]));
}

// ---------------- scratch (device globals; no runtime allocation) ----------
__device__ float2 g_F2[BCn*Ln*NPOS];    // compact 2D-DFT (kw<=28) ~53MB
__device__ float  g_y[NTOT];            // pre-BN conv output (~51MB)
__device__ float  g_ppart[BCn*4*Ln];    // pooled partials (deterministic reduce)
__device__ float  g_s[BLn*Cn];          // per (b,l,ci) input-channel scale
__device__ float  g_fb[BLn*Cn];         // per (b,l,co) dynamic bias
__device__ float  g_bnsum2[Cn*NBLK];    // BN partial sums per (co, bl*28+tile)
__device__ float  g_bnsq2[Cn*NBLK];
__device__ float  g_mean[Cn];
__device__ float  g_invstd[Cn];

// ============================================================================
// K1: 2D DFT per (b,c,l) slab; TWO slabs per block (threads 0-111 / 112-223).
// Hermitian: compute kw in [0,31], store only kw<=28 compactly (stride 29).
// f32x2 complex MACs. Dynamic smem: 86016 B.   (unchanged from best)
// ============================================================================
__global__ __launch_bounds__(224) void k1_dft2d(const float* __restrict__ x) {
    extern __shared__ char k1sm[];
    u64*   t1a = (u64*)k1sm;              // [2][56*33] (re,im)
    u64*   t1s = t1a + 2*56*33;           // [2][56*33] (im,re)
    u64*   twp = t1s + 2*56*33;           // 56  (c,s)
    u64*   twA = twp + 56;                // 56  (c,c)
    u64*   twB = twA + 56;                // 56  (-s,s)
    float* xs  = (float*)(twB + 56);      // [2][56*57]

    int bid = blockIdx.x;                 // bc*4 + lpair
    int bc  = bid >> 2;
    int lp  = bid & 3;
    int b   = bc >> 6;
    int c   = bc & 63;
    int tid = threadIdx.x;
    int s   = (tid >= 112) ? 1 : 0;
    int loc = tid - s*112;                // 0..111
    int l   = lp*2 + s;

    float* xss = xs  + s*(56*57);
    u64*   t1A = t1a + s*(56*33);
    u64*   t1S = t1s + s*(56*33);

    const float* xp = x + (size_t)((b*Ln + l)*Cn + c) * HWn;
    #pragma unroll
    for (int k = 0; k < 28; ++k) {
        int e = loc + k*112;
        xss[(e/56)*57 + (e%56)] = xp[e];
    }
    if (tid < 56) {
        float sv, cv;
        sincosf(-6.28318530717958647692f * (float)tid / 56.0f, &sv, &cv);
        twp[tid] = pack2(cv, sv);
        twA[tid] = pack2(cv, cv);
        twB[tid] = pack2(-sv, sv);
    }
    __syncthreads();

    int th = loc >> 3;                    // 0..13
    int tk = loc & 7;                     // 0..7
    int h0  = th * 4;
    int kw0 = tk * 4;                     // kw in [0,32)

    {
        u64 acc2[4][4];
        #pragma unroll
        for (int i = 0; i < 4; ++i)
            #pragma unroll
            for (int j = 0; j < 4; ++j) acc2[i][j] = 0ull;
        int idx[4] = {0, 0, 0, 0};
        for (int w = 0; w < 56; ++w) {
            u64 xa2[4];
            #pragma unroll
            for (int i = 0; i < 4; ++i) {
                float v = xss[(h0 + i)*57 + w];
                xa2[i] = pack2(v, v);
            }
            #pragma unroll
            for (int j = 0; j < 4; ++j) {
                u64 t = twp[idx[j]];
                #pragma unroll
                for (int i = 0; i < 4; ++i)
                    acc2[i][j] = ffma2(xa2[i], t, acc2[i][j]);
                idx[j] += kw0 + j;
                if (idx[j] >= 56) idx[j] -= 56;
            }
        }
        #pragma unroll
        for (int i = 0; i < 4; ++i)
            #pragma unroll
            for (int j = 0; j < 4; ++j) {
                int o = (h0 + i)*33 + kw0 + j;
                t1A[o] = acc2[i][j];
                float2 v = unpack2(acc2[i][j]);
                t1S[o] = pack2(v.y, v.x);
            }
    }
    __syncthreads();

    {
        u64 acc2[4][4];
        #pragma unroll
        for (int i = 0; i < 4; ++i)
            #pragma unroll
            for (int j = 0; j < 4; ++j) acc2[i][j] = 0ull;
        int idx[4] = {0, 0, 0, 0};
        for (int h = 0; h < 56; ++h) {
            u64 tA[4], tB[4];
            #pragma unroll
            for (int i = 0; i < 4; ++i) {
                tA[i] = twA[idx[i]];
                tB[i] = twB[idx[i]];
                idx[i] += h0 + i;
                if (idx[i] >= 56) idx[i] -= 56;
            }
            u64 ua[4], us[4];
            #pragma unroll
            for (int j = 0; j < 4; ++j) {
                ua[j] = t1A[h*33 + kw0 + j];
                us[j] = t1S[h*33 + kw0 + j];
            }
            #pragma unroll
            for (int i = 0; i < 4; ++i)
                #pragma unroll
                for (int j = 0; j < 4; ++j) {
                    acc2[i][j] = ffma2(tA[i], ua[j], acc2[i][j]);
                    acc2[i][j] = ffma2(tB[i], us[j], acc2[i][j]);
                }
        }
        float2* outp = g_F2 + (size_t)(bc*Ln + l) * NPOS;
        #pragma unroll
        for (int i = 0; i < 4; ++i) {
            int kh = h0 + i;
            #pragma unroll
            for (int j = 0; j < 4; ++j) {
                int kw = kw0 + j;
                if (kw <= 28) {
                    float2 v = unpack2(acc2[i][j]);
                    outp[kh*KWC + kw] = v;
                }
            }
        }
    }
}

// ============================================================================
// K2: 8-point DFT along L + magnitude at compact positions; mirror reuse.
// (unchanged from best)
// ============================================================================
__global__ __launch_bounds__(448) void k2_ldft(const float* __restrict__ x) {
    int bx = blockIdx.x;
    int bc = bx >> 2, jb = bx & 3;
    int b  = bc >> 6, c = bc & 63;
    int tid = threadIdx.x;
    int idx = jb * 448 + tid;             // 0..1791

    float contrib[8];
    #pragma unroll
    for (int k = 0; k < 8; ++k) contrib[k] = 0.f;

    if (idx < NPOS) {
        int kh = idx / KWC, kw = idx % KWC;
        int p  = kh*56 + kw;
        int pm = ((56 - kh) % 56)*56 + ((56 - kw) % 56);
        bool do_m = (kw >= 1 && kw <= 27);

        const float2* f2 = g_F2 + (size_t)(bc*Ln) * NPOS + idx;
        float fr[8], fi[8];
        #pragma unroll
        for (int l2 = 0; l2 < 8; ++l2) {
            float2 v = f2[(size_t)l2 * NPOS];
            fr[l2] = v.x; fi[l2] = v.y;
        }

        const float RT = 0.70710678118654752f;
        const float twc[8] = {1.f,  RT, 0.f, -RT, -1.f, -RT, 0.f,  RT};
        const float tws[8] = {0.f, -RT, -1.f, -RT, 0.f,  RT, 1.f,  RT};
        const float SCALE = 0.01f / 158.39507568359375f;   // 0.01/sqrt(8*56*56)

        float mag[8];
        #pragma unroll
        for (int k = 0; k < 8; ++k) {
            float re = 0.f, im = 0.f;
            #pragma unroll
            for (int l2 = 0; l2 < 8; ++l2) {
                int j = (l2 * k) & 7;
                re += twc[j]*fr[l2] - tws[j]*fi[l2];
                im += twc[j]*fi[l2] + tws[j]*fr[l2];
            }
            mag[k] = sqrtf(re*re + im*im);
        }

        #pragma unroll
        for (int k = 0; k < 8; ++k) {
            const float* xl = x + (size_t)((b*Ln + k)*Cn + c) * HWn;
            float v = xl[p] * (1.0f + SCALE * mag[k]);
            if (do_m)
                v += xl[pm] * (1.0f + SCALE * mag[(8 - k) & 7]);
            contrib[k] = v;
        }
    }

    #pragma unroll
    for (int k = 0; k < 8; ++k)
        #pragma unroll
        for (int off = 16; off > 0; off >>= 1)
            contrib[k] += __shfl_down_sync(0xffffffff, contrib[k], off);

    __shared__ float ws[14][8];
    int wid = tid >> 5, lane = tid & 31;
    if (lane == 0) {
        #pragma unroll
        for (int k = 0; k < 8; ++k) ws[wid][k] = contrib[k];
    }
    __syncthreads();
    if (tid < 8) {
        float s = 0.f;
        #pragma unroll
        for (int w2 = 0; w2 < 14; ++w2) s += ws[w2][tid];
        g_ppart[(bc*4 + jb)*8 + tid] = s;
    }
}

// ============================================================================
// K3: pooled -> calibration scale s[b,l,ci] and dynamic bias fb[b,l,co].
// (unchanged from best)
// ============================================================================
__global__ __launch_bounds__(64) void k3_calib(
    const float* __restrict__ tw_, const float* __restrict__ tb,
    const float* __restrict__ fcw, const float* __restrict__ fcb,
    const float* __restrict__ convb)
{
    int bl = blockIdx.x;
    int b  = bl >> 3, l = bl & 7;
    int tid = threadIdx.x;

    __shared__ float pooled[64];
    __shared__ float fcp[65];

    float s = 0.f;
    #pragma unroll
    for (int j = 0; j < 4; ++j)
        s += g_ppart[((b*Cn + tid)*4 + j)*8 + l];
    float pv = s * (1.0f / 3136.0f);
    pooled[tid] = pv;
    fcp[tid] = fcw[tid] * pv;
    __syncthreads();

    float calib = tb[tid];
    #pragma unroll 8
    for (int c = 0; c < 64; ++c) calib += tw_[tid*64 + c] * pooled[c];
    g_s[bl*Cn + tid] = calib + 1.0f;

    if (tid == 0) {
        float f = fcb[0];
        for (int c = 0; c < 64; ++c) f += fcp[c];
        fcp[64] = f + 1.0f;
    }
    __syncthreads();
    g_fb[bl*Cn + tid] = convb[tid] * fcp[64];
}

// ============================================================================
// K4T: conv3x3 as tf32 implicit GEMM via mma.sync.m16n8k8.
//   D[co, px] = sum_{k=ci*9+tap} A[co,k] * B[k,px];  M=64, K=576, N=112/block.
// Block = (tile of 2 output rows, bl). 448 threads = 14 warps:
//   warp w: mw = w&1 (m32 half: co base mw*32), nw = w>>1 (n16 strip).
// smem (dynamic, u32):
//   xs  [64ci][4rows][60]  tf32 x tile with halo (rows 2t-1..2t+2)
//   As  [36kk][4tg][65co][2] tf32 weights*scale, pre-paired (k, k+4) for LDS.64
//   kOff[576]              B descriptor: ci*240 + dr*60 + dc
// A staged in two K-halves (288 each). Epilogue: +fb +residual, write g_y,
// deterministic BN partials to g_bnsum2/g_bnsq2[co][bl*28+tile].
// ============================================================================
#define K4T_SMEM ((15360 + 18720 + 576) * 4)   // 138,624 B

__global__ __launch_bounds__(448, 1) void k4t_conv(const float* __restrict__ x,
                                                   const float* __restrict__ convw) {
    extern __shared__ uint32_t dsm[];
    uint32_t* xs   = dsm;                   // 15360 u32
    uint32_t* As   = dsm + 15360;           // 18720 u32
    uint32_t* kOff = dsm + 15360 + 18720;   // 576 u32
    __shared__ float ssh[64];
    __shared__ float red_s[14][32];
    __shared__ float red_q[14][32];

    int tile = blockIdx.x;   // 0..27
    int bl   = blockIdx.y;   // 0..63
    int tid  = threadIdx.x;
    int w    = tid >> 5;
    int lane = tid & 31;
    int g    = lane >> 2;    // 0..7
    int tg   = lane & 3;     // 0..3
    int mw   = w & 1;
    int nw   = w >> 1;       // 0..6
    int mwbase = mw * 32;

    if (tid < 64) ssh[tid] = g_s[bl*64 + tid];

    for (int k = tid; k < 576; k += 448) {
        int ci = k / 9, tap = k - 9*ci, dr = tap / 3, dc = tap - 3*dr;
        kOff[k] = (uint32_t)(ci*240 + dr*60 + dc);
    }

    const float* xb = x + (size_t)bl * 64 * HWn;
    for (int e = tid; e < 64*4*58; e += 448) {
        int c = e % 58; int t = e / 58; int r = t & 3; int ci = t >> 2;
        int gr = 2*tile - 1 + r; int gc = c - 1;
        float v = 0.f;
        if (gr >= 0 && gr < 56 && gc >= 0 && gc < 56)
            v = xb[ci*HWn + gr*56 + gc];
        xs[ci*240 + r*60 + c] = f2tf32(v);
    }
    __syncthreads();

    uint32_t pxoff[2];
    #pragma unroll
    for (int nf = 0; nf < 2; ++nf) {
        int px = nw*16 + nf*8 + g;
        int rs = (px >= 56) ? 1 : 0;
        pxoff[nf] = (uint32_t)(rs*60 + (px - rs*56));
    }

    float acc[2][2][4];
    #pragma unroll
    for (int mf = 0; mf < 2; ++mf)
        #pragma unroll
        for (int nf = 0; nf < 2; ++nf)
            #pragma unroll
            for (int j = 0; j < 4; ++j) acc[mf][nf][j] = 0.f;

    for (int half = 0; half < 2; ++half) {
        // stage A half: k in [half*288, half*288+288)
        for (int e = tid; e < 18432; e += 448) {
            int j = e & 1; int t = e >> 1;
            int co = t & 63; t >>= 6;
            int tg2 = t & 3; int kk = t >> 2;          // kk 0..35
            int k = half*288 + kk*8 + tg2 + 4*j;
            int ci = k / 9, tap = k - 9*ci;
            float v = convw[(co*64 + ci)*9 + tap] * ssh[ci];
            As[((kk*4 + tg2)*65 + co)*2 + j] = f2tf32(v);
        }
        __syncthreads();

        int kbase = half * 288;
        for (int kk = 0; kk < 36; ++kk) {
            uint32_t ko0 = kOff[kbase + kk*8 + tg];
            uint32_t ko4 = kOff[kbase + kk*8 + tg + 4];

            uint32_t a[2][4];
            #pragma unroll
            for (int mf = 0; mf < 2; ++mf) {
                int ub = (kk*4 + tg)*65 + mwbase + mf*16 + g;
                uint2 p0 = *(const uint2*)(As + 2*ub);          // (a0, a2) at row g
                uint2 p1 = *(const uint2*)(As + 2*(ub + 8));    // (a1, a3) at row g+8
                a[mf][0] = p0.x; a[mf][1] = p1.x; a[mf][2] = p0.y; a[mf][3] = p1.y;
            }
            uint32_t b[2][2];
            #pragma unroll
            for (int nf = 0; nf < 2; ++nf) {
                b[nf][0] = xs[ko0 + pxoff[nf]];
                b[nf][1] = xs[ko4 + pxoff[nf]];
            }
            #pragma unroll
            for (int mf = 0; mf < 2; ++mf)
                #pragma unroll
                for (int nf = 0; nf < 2; ++nf)
                    mma_tf32(acc[mf][nf], a[mf], b[nf]);
        }
        __syncthreads();   // all warps done with As before restage / epilogue
    }

    // ---- epilogue: + fb + residual, write y, BN partials -------------------
    float psum[2][2] = {{0.f,0.f},{0.f,0.f}};
    float psq [2][2] = {{0.f,0.f},{0.f,0.f}};
    #pragma unroll
    for (int mf = 0; mf < 2; ++mf) {
        #pragma unroll
        for (int nf = 0; nf < 2; ++nf) {
            #pragma unroll
            for (int j = 0; j < 4; ++j) {
                int hi = j >> 1;
                int co = mwbase + mf*16 + g + hi*8;
                int px = nw*16 + nf*8 + tg*2 + (j & 1);
                int rs = (px >= 56) ? 1 : 0;
                int row = 2*tile + rs;
                int col = px - rs*56;
                int loc = co*HWn + row*56 + col;
                float v = acc[mf][nf][j] + g_fb[bl*64 + co] + xb[loc];
                g_y[(size_t)bl*64*HWn + loc] = v;
                psum[mf][hi] += v;
                psq [mf][hi] += v*v;
            }
        }
    }
    #pragma unroll
    for (int mf = 0; mf < 2; ++mf)
        #pragma unroll
        for (int hi = 0; hi < 2; ++hi) {
            float s = psum[mf][hi], q = psq[mf][hi];
            s += __shfl_down_sync(0xffffffffu, s, 2, 4);
            s += __shfl_down_sync(0xffffffffu, s, 1, 4);
            q += __shfl_down_sync(0xffffffffu, q, 2, 4);
            q += __shfl_down_sync(0xffffffffu, q, 1, 4);
            if (tg == 0) {
                red_s[w][mf*16 + hi*8 + g] = s;
                red_q[w][mf*16 + hi*8 + g] = q;
            }
        }
    __syncthreads();
    if (tid < 64) {
        int co = tid;
        int mw2 = co >> 5; int rem = co & 31;
        int mf = rem >> 4; int g8 = rem & 15;
        int hi = g8 >> 3;  int g2 = g8 & 7;
        int idx = mf*16 + hi*8 + g2;
        float s = 0.f, q = 0.f;
        #pragma unroll
        for (int nw2 = 0; nw2 < 7; ++nw2) {
            s += red_s[nw2*2 + mw2][idx];
            q += red_q[nw2*2 + mw2][idx];
        }
        g_bnsum2[co*NBLK + bl*TILES + tile] = s;
        g_bnsq2 [co*NBLK + bl*TILES + tile] = q;
    }
}

// ============================================================================
// K4b: final BN statistics. 64 blocks (one per channel), 256 threads,
// deterministic fixed-stride + shuffle-tree reduction over 1792 partials.
// ============================================================================
__global__ __launch_bounds__(256) void k4b_stats() {
    int co  = blockIdx.x;
    int tid = threadIdx.x;
    float s = 0.f, q = 0.f;
    for (int i = tid; i < NBLK; i += 256) {
        s += g_bnsum2[co*NBLK + i];
        q += g_bnsq2 [co*NBLK + i];
    }
    #pragma unroll
    for (int off = 16; off > 0; off >>= 1) {
        s += __shfl_down_sync(0xffffffffu, s, off);
        q += __shfl_down_sync(0xffffffffu, q, off);
    }
    __shared__ float ws2[8], wq2[8];
    int wid = tid >> 5, lane = tid & 31;
    if (lane == 0) { ws2[wid] = s; wq2[wid] = q; }
    __syncthreads();
    if (tid == 0) {
        float S = 0.f, Q = 0.f;
        #pragma unroll
        for (int i = 0; i < 8; ++i) { S += ws2[i]; Q += wq2[i]; }
        const float invN = 1.0f / (float)(BLn * HWn);
        float mean = S * invN;
        float var  = Q * invN - mean*mean;
        g_mean[co]   = mean;
        g_invstd[co] = rsqrtf(var + 1e-5f);
    }
}

// ============================================================================
// K5: BN normalize + affine + SiLU -> d_out (float4 vectorized)  (unchanged)
// ============================================================================
__global__ __launch_bounds__(256) void k5_bnsilu(const float* __restrict__ gamma,
                                                 const float* __restrict__ beta,
                                                 float* __restrict__ out) {
    int i4 = blockIdx.x * 256 + threadIdx.x;
    int c = ((i4 * 4) / HWn) & 63;
    float4 y = ((const float4*)g_y)[i4];
    float m = g_mean[c], is = g_invstd[c] * gamma[c], bt = beta[c];
    float4 o;
    o.x = (y.x - m) * is + bt;
    o.y = (y.y - m) * is + bt;
    o.z = (y.z - m) * is + bt;
    o.w = (y.w - m) * is + bt;
    o.x = o.x / (1.0f + __expf(-o.x));
    o.y = o.y / (1.0f + __expf(-o.y));
    o.z = o.z / (1.0f + __expf(-o.z));
    o.w = o.w / (1.0f + __expf(-o.w));
    ((float4*)out)[i4] = o;
}

// ============================================================================
extern "C" void kernel_launch(void* const* d_in, const int* in_sizes, int n_in,
                              void* d_out, int out_size) {
    const float* x          = (const float*)d_in[0];
    const float* temporal_w = (const float*)d_in[1];
    const float* temporal_b = (const float*)d_in[2];
    const float* fc_w       = (const float*)d_in[3];
    const float* fc_b       = (const float*)d_in[4];
    const float* conv_w     = (const float*)d_in[5];
    const float* conv_b     = (const float*)d_in[6];
    const float* bn_gamma   = (const float*)d_in[7];
    const float* bn_beta    = (const float*)d_in[8];
    float* out = (float*)d_out;

    const int K1_SMEM = (2*56*33*2)*8 + 3*56*8 + (2*56*57)*4;   // 86016 B
    static int configured = 0;
    if (!configured) {
        cudaFuncSetAttribute(k1_dft2d, cudaFuncAttributeMaxDynamicSharedMemorySize, K1_SMEM);
        cudaFuncSetAttribute(k4t_conv, cudaFuncAttributeMaxDynamicSharedMemorySize, K4T_SMEM);
        configured = 1;
    }

    k1_dft2d<<<BCn*Ln/2, 224, K1_SMEM>>>(x);      // 2048 blocks, 2 slabs each
    k2_ldft<<<BCn*4, 448>>>(x);                   // 2048 blocks
    k3_calib<<<BLn, 64>>>(temporal_w, temporal_b, fc_w, fc_b, conv_b);
    k4t_conv<<<dim3(TILES, BLn), 448, K4T_SMEM>>>(x, conv_w);   // 1792 blocks
    k4b_stats<<<Cn, 256>>>();
    k5_bnsilu<<<NTOT/1024, 256>>>(bn_gamma, bn_beta, out);
}

// round 10
// speedup vs baseline: 1.5792x; 1.5792x over previous
#include <cuda_runtime.h>
#include <math.h>
#include <stdint.h>

#define Bn 8
#define Ln 8
#define Cn 64
#define Hn 56
#define Wn 56
#define HWn 3136
#define BCn (Bn*Cn)        // 512
#define BLn (Bn*Ln)        // 64
#define NTOT (BLn*Cn*HWn)  // 12,845,056
#define KWC 29             // compact kw count (Hermitian half)
#define NPOS (56*KWC)      // 1624 positions per slab
#define TILES 28           // k4t: 2 output rows per tile
#define NBLK (BLn*TILES)   // 1792 BN-partial slots

typedef unsigned long long u64;

__device__ __forceinline__ u64 ffma2(u64 a, u64 b, u64 c) {
    u64 d;
    asm("fma.rn.f32x2 %0, %1, %2, %3;" : "=l"(d) : "l"(a), "l"(b), "l"(c));
    return d;
}
__device__ __forceinline__ u64 pack2(float lo, float hi) {
    u64 d;
    asm("mov.b64 %0, {%1, %2};" : "=l"(d) : "f"(lo), "f"(hi));
    return d;
}
__device__ __forceinline__ float2 unpack2(u64 v) {
    float2 r;
    asm("mov.b64 {%0, %1}, %2;" : "=f"(r.x), "=f"(r.y) : "l"(v));
    return r;
}
__device__ __forceinline__ uint32_t f2tf32(float v) {
    uint32_t b;
    asm("cvt.rna.tf32.f32 %0, %1;" : "=r"(b) : "f"(v));
    return b;
}
__device__ __forceinline__ void mma_tf32(float* d, const uint32_t* a, const uint32_t* b) {
    asm volatile(
        "mma.sync.aligned.m16n8k8.row.col.f32.tf32.tf32.f32 "
        "{%0,%1,%2,%3}, {%4,%5,%6,%7}, {%8,%9}, {%0,%1,%2,%3};\n"
        : "+f"(d[0]), "+f"(d[1]), "+f"(d[2]), "+f"(d[3])
        : "r"(a[0]), "r"(a[1]), "r"(a[2]), "r"(a[3]), "r"(b[0]), "r"(b[1]));
}

// ---------------- scratch (device globals; no runtime allocation) ----------
__device__ float2 g_F2[BCn*Ln*NPOS];    // compact 2D-DFT (kw<=28) ~53MB
__device__ float  g_y[NTOT];            // pre-BN conv output (~51MB)
__device__ float  g_ppart[BCn*4*Ln];    // pooled partials
__device__ float  g_s[BLn*Cn];          // per (b,l,ci) input-channel scale
__device__ float  g_fb[BLn*Cn];         // per (b,l,co) dynamic bias
__device__ __align__(16) uint32_t g_Atf[72*512];  // tf32 weights, swizzled [kkg][co][8]
__device__ float  g_bnsum2[Cn*NBLK];
__device__ float  g_bnsq2[Cn*NBLK];
__device__ float  g_mean[Cn];
__device__ float  g_invstd[Cn];

// ============================================================================
// K0: one-shot A preparation: convw -> tf32, laid out [kkg][co][pair j] with
// the smem bank-swizzle (tg ^ (co&3)) baked in so block staging is raw copy.
// ============================================================================
__global__ __launch_bounds__(512) void k0_aprep(const float* __restrict__ convw) {
    int e = blockIdx.x*512 + threadIdx.x;   // 72*512 = 36864
    int j  = e & 1;  int t = e >> 1;
    int tg = t & 3;  t >>= 2;
    int co = t & 63; int kkg = t >> 6;      // 0..71
    int k  = kkg*8 + tg + 4*j;
    int ci = k / 9, tap = k - 9*ci;
    g_Atf[kkg*512 + co*8 + ((tg ^ (co & 3)) << 1) + j] =
        f2tf32(convw[(co*64 + ci)*9 + tap]);
}

// ============================================================================
// K1: 2D DFT per (b,c,l) slab; TWO slabs per block. Hermitian compact store.
// (unchanged from best)
// ============================================================================
__global__ __launch_bounds__(224) void k1_dft2d(const float* __restrict__ x) {
    extern __shared__ char k1sm[];
    u64*   t1a = (u64*)k1sm;
    u64*   t1s = t1a + 2*56*33;
    u64*   twp = t1s + 2*56*33;
    u64*   twA = twp + 56;
    u64*   twB = twA + 56;
    float* xs  = (float*)(twB + 56);

    int bid = blockIdx.x;
    int bc  = bid >> 2;
    int lp  = bid & 3;
    int b   = bc >> 6;
    int c   = bc & 63;
    int tid = threadIdx.x;
    int s   = (tid >= 112) ? 1 : 0;
    int loc = tid - s*112;
    int l   = lp*2 + s;

    float* xss = xs  + s*(56*57);
    u64*   t1A = t1a + s*(56*33);
    u64*   t1S = t1s + s*(56*33);

    const float* xp = x + (size_t)((b*Ln + l)*Cn + c) * HWn;
    #pragma unroll
    for (int k = 0; k < 28; ++k) {
        int e = loc + k*112;
        xss[(e/56)*57 + (e%56)] = xp[e];
    }
    if (tid < 56) {
        float sv, cv;
        sincosf(-6.28318530717958647692f * (float)tid / 56.0f, &sv, &cv);
        twp[tid] = pack2(cv, sv);
        twA[tid] = pack2(cv, cv);
        twB[tid] = pack2(-sv, sv);
    }
    __syncthreads();

    int th = loc >> 3;
    int tk = loc & 7;
    int h0  = th * 4;
    int kw0 = tk * 4;

    {
        u64 acc2[4][4];
        #pragma unroll
        for (int i = 0; i < 4; ++i)
            #pragma unroll
            for (int j = 0; j < 4; ++j) acc2[i][j] = 0ull;
        int idx[4] = {0, 0, 0, 0};
        for (int w = 0; w < 56; ++w) {
            u64 xa2[4];
            #pragma unroll
            for (int i = 0; i < 4; ++i) {
                float v = xss[(h0 + i)*57 + w];
                xa2[i] = pack2(v, v);
            }
            #pragma unroll
            for (int j = 0; j < 4; ++j) {
                u64 t = twp[idx[j]];
                #pragma unroll
                for (int i = 0; i < 4; ++i)
                    acc2[i][j] = ffma2(xa2[i], t, acc2[i][j]);
                idx[j] += kw0 + j;
                if (idx[j] >= 56) idx[j] -= 56;
            }
        }
        #pragma unroll
        for (int i = 0; i < 4; ++i)
            #pragma unroll
            for (int j = 0; j < 4; ++j) {
                int o = (h0 + i)*33 + kw0 + j;
                t1A[o] = acc2[i][j];
                float2 v = unpack2(acc2[i][j]);
                t1S[o] = pack2(v.y, v.x);
            }
    }
    __syncthreads();

    {
        u64 acc2[4][4];
        #pragma unroll
        for (int i = 0; i < 4; ++i)
            #pragma unroll
            for (int j = 0; j < 4; ++j) acc2[i][j] = 0ull;
        int idx[4] = {0, 0, 0, 0};
        for (int h = 0; h < 56; ++h) {
            u64 tA[4], tB[4];
            #pragma unroll
            for (int i = 0; i < 4; ++i) {
                tA[i] = twA[idx[i]];
                tB[i] = twB[idx[i]];
                idx[i] += h0 + i;
                if (idx[i] >= 56) idx[i] -= 56;
            }
            u64 ua[4], us[4];
            #pragma unroll
            for (int j = 0; j < 4; ++j) {
                ua[j] = t1A[h*33 + kw0 + j];
                us[j] = t1S[h*33 + kw0 + j];
            }
            #pragma unroll
            for (int i = 0; i < 4; ++i)
                #pragma unroll
                for (int j = 0; j < 4; ++j) {
                    acc2[i][j] = ffma2(tA[i], ua[j], acc2[i][j]);
                    acc2[i][j] = ffma2(tB[i], us[j], acc2[i][j]);
                }
        }
        float2* outp = g_F2 + (size_t)(bc*Ln + l) * NPOS;
        #pragma unroll
        for (int i = 0; i < 4; ++i) {
            int kh = h0 + i;
            #pragma unroll
            for (int j = 0; j < 4; ++j) {
                int kw = kw0 + j;
                if (kw <= 28) {
                    float2 v = unpack2(acc2[i][j]);
                    outp[kh*KWC + kw] = v;
                }
            }
        }
    }
}

// ============================================================================
// K2: 8-point DFT along L + magnitude; mirror reuse. (unchanged from best)
// ============================================================================
__global__ __launch_bounds__(448) void k2_ldft(const float* __restrict__ x) {
    int bx = blockIdx.x;
    int bc = bx >> 2, jb = bx & 3;
    int b  = bc >> 6, c = bc & 63;
    int tid = threadIdx.x;
    int idx = jb * 448 + tid;

    float contrib[8];
    #pragma unroll
    for (int k = 0; k < 8; ++k) contrib[k] = 0.f;

    if (idx < NPOS) {
        int kh = idx / KWC, kw = idx % KWC;
        int p  = kh*56 + kw;
        int pm = ((56 - kh) % 56)*56 + ((56 - kw) % 56);
        bool do_m = (kw >= 1 && kw <= 27);

        const float2* f2 = g_F2 + (size_t)(bc*Ln) * NPOS + idx;
        float fr[8], fi[8];
        #pragma unroll
        for (int l2 = 0; l2 < 8; ++l2) {
            float2 v = f2[(size_t)l2 * NPOS];
            fr[l2] = v.x; fi[l2] = v.y;
        }

        const float RT = 0.70710678118654752f;
        const float twc[8] = {1.f,  RT, 0.f, -RT, -1.f, -RT, 0.f,  RT};
        const float tws[8] = {0.f, -RT, -1.f, -RT, 0.f,  RT, 1.f,  RT};
        const float SCALE = 0.01f / 158.39507568359375f;

        float mag[8];
        #pragma unroll
        for (int k = 0; k < 8; ++k) {
            float re = 0.f, im = 0.f;
            #pragma unroll
            for (int l2 = 0; l2 < 8; ++l2) {
                int j = (l2 * k) & 7;
                re += twc[j]*fr[l2] - tws[j]*fi[l2];
                im += twc[j]*fi[l2] + tws[j]*fr[l2];
            }
            mag[k] = sqrtf(re*re + im*im);
        }

        #pragma unroll
        for (int k = 0; k < 8; ++k) {
            const float* xl = x + (size_t)((b*Ln + k)*Cn + c) * HWn;
            float v = xl[p] * (1.0f + SCALE * mag[k]);
            if (do_m)
                v += xl[pm] * (1.0f + SCALE * mag[(8 - k) & 7]);
            contrib[k] = v;
        }
    }

    #pragma unroll
    for (int k = 0; k < 8; ++k)
        #pragma unroll
        for (int off = 16; off > 0; off >>= 1)
            contrib[k] += __shfl_down_sync(0xffffffff, contrib[k], off);

    __shared__ float ws[14][8];
    int wid = tid >> 5, lane = tid & 31;
    if (lane == 0) {
        #pragma unroll
        for (int k = 0; k < 8; ++k) ws[wid][k] = contrib[k];
    }
    __syncthreads();
    if (tid < 8) {
        float s = 0.f;
        #pragma unroll
        for (int w2 = 0; w2 < 14; ++w2) s += ws[w2][tid];
        g_ppart[(bc*4 + jb)*8 + tid] = s;
    }
}

// ============================================================================
// K3: pooled -> calibration. (unchanged from best)
// ============================================================================
__global__ __launch_bounds__(64) void k3_calib(
    const float* __restrict__ tw_, const float* __restrict__ tb,
    const float* __restrict__ fcw, const float* __restrict__ fcb,
    const float* __restrict__ convb)
{
    int bl = blockIdx.x;
    int b  = bl >> 3, l = bl & 7;
    int tid = threadIdx.x;

    __shared__ float pooled[64];
    __shared__ float fcp[65];

    float s = 0.f;
    #pragma unroll
    for (int j = 0; j < 4; ++j)
        s += g_ppart[((b*Cn + tid)*4 + j)*8 + l];
    float pv = s * (1.0f / 3136.0f);
    pooled[tid] = pv;
    fcp[tid] = fcw[tid] * pv;
    __syncthreads();

    float calib = tb[tid];
    #pragma unroll 8
    for (int c = 0; c < 64; ++c) calib += tw_[tid*64 + c] * pooled[c];
    g_s[bl*Cn + tid] = calib + 1.0f;

    if (tid == 0) {
        float f = fcb[0];
        for (int c = 0; c < 64; ++c) f += fcp[c];
        fcp[64] = f + 1.0f;
    }
    __syncthreads();
    g_fb[bl*Cn + tid] = convb[tid] * fcp[64];
}

// ============================================================================
// K4T v2: tf32 implicit-GEMM conv. Scale folded into B (x tile), A constant
// and pre-swizzled in g_Atf (raw uint4 staging), K staged in 4 quarters of
// 144 -> smem 100.6KB -> 2 blocks/SM. Conflict-free A LDS.64 via (tg^(g&3)).
// ============================================================================
#define K4T_SMEM ((15360 + 9216 + 576) * 4)   // 100,608 B

__global__ __launch_bounds__(448, 2) void k4t_conv(const float* __restrict__ x,
                                                   const float* __restrict__ convw) {
    extern __shared__ uint32_t dsm[];
    uint32_t* xs   = dsm;                   // 15360 u32: [64ci][4r][60]
    uint32_t* As   = dsm + 15360;           // 9216 u32: quarter [18kk][64co][8]
    uint32_t* kOff = dsm + 15360 + 9216;    // 576 u32
    __shared__ float ssh[64];
    __shared__ float red_s[14][32];
    __shared__ float red_q[14][32];

    int tile = blockIdx.x;   // 0..27
    int bl   = blockIdx.y;   // 0..63
    int tid  = threadIdx.x;
    int w    = tid >> 5;
    int lane = tid & 31;
    int g    = lane >> 2;    // 0..7
    int tg   = lane & 3;     // 0..3
    int mw   = w & 1;
    int nw   = w >> 1;       // 0..6
    int mwbase = mw * 32;

    if (tid < 64) ssh[tid] = g_s[bl*64 + tid];
    for (int k = tid; k < 576; k += 448) {
        int ci = k / 9, tap = k - 9*ci, dr = tap / 3, dc = tap - 3*dr;
        kOff[k] = (uint32_t)(ci*240 + dr*60 + dc);
    }
    __syncthreads();        // ssh ready before xs staging uses it

    const float* xb = x + (size_t)bl * 64 * HWn;
    for (int e = tid; e < 64*4*58; e += 448) {
        int c = e % 58; int t = e / 58; int r = t & 3; int ci = t >> 2;
        int gr = 2*tile - 1 + r; int gc = c - 1;
        float v = 0.f;
        if (gr >= 0 && gr < 56 && gc >= 0 && gc < 56)
            v = xb[ci*HWn + gr*56 + gc] * ssh[ci];
        xs[ci*240 + r*60 + c] = f2tf32(v);
    }

    uint32_t pxoff[2];
    #pragma unroll
    for (int nf = 0; nf < 2; ++nf) {
        int px = nw*16 + nf*8 + g;
        int rs = (px >= 56) ? 1 : 0;
        pxoff[nf] = (uint32_t)(rs*60 + (px - rs*56));
    }
    int swz = ((tg ^ (g & 3)) << 1);

    float acc[2][2][4];
    #pragma unroll
    for (int mf = 0; mf < 2; ++mf)
        #pragma unroll
        for (int nf = 0; nf < 2; ++nf)
            #pragma unroll
            for (int j = 0; j < 4; ++j) acc[mf][nf][j] = 0.f;

    for (int q = 0; q < 4; ++q) {
        // stage A quarter: raw uint4 copy (swizzle baked in by k0)
        __syncthreads();    // prior quarter's As reads done; xs ready on q=0
        {
            const uint4* srcv = (const uint4*)(g_Atf + q*9216);
            uint4* dstv = (uint4*)As;
            for (int e = tid; e < 2304; e += 448) dstv[e] = srcv[e];
        }
        __syncthreads();

        int kbase = q*144;
        #pragma unroll 2
        for (int kk = 0; kk < 18; ++kk) {
            uint32_t ko0 = kOff[kbase + kk*8 + tg];
            uint32_t ko4 = kOff[kbase + kk*8 + tg + 4];

            uint32_t a[2][4];
            #pragma unroll
            for (int mf = 0; mf < 2; ++mf) {
                const uint32_t* base0 = As + kk*512 + (mwbase + mf*16 + g)*8 + swz;
                uint2 p0 = *(const uint2*)base0;          // rows g:   (a0, a2)
                uint2 p1 = *(const uint2*)(base0 + 64);   // rows g+8: (a1, a3)
                a[mf][0] = p0.x; a[mf][1] = p1.x; a[mf][2] = p0.y; a[mf][3] = p1.y;
            }
            uint32_t b[2][2];
            #pragma unroll
            for (int nf = 0; nf < 2; ++nf) {
                b[nf][0] = xs[ko0 + pxoff[nf]];
                b[nf][1] = xs[ko4 + pxoff[nf]];
            }
            #pragma unroll
            for (int mf = 0; mf < 2; ++mf)
                #pragma unroll
                for (int nf = 0; nf < 2; ++nf)
                    mma_tf32(acc[mf][nf], a[mf], b[nf]);
        }
    }
    __syncthreads();

    // ---- epilogue: + fb + residual, write y, BN partials -------------------
    float psum[2][2] = {{0.f,0.f},{0.f,0.f}};
    float psq [2][2] = {{0.f,0.f},{0.f,0.f}};
    #pragma unroll
    for (int mf = 0; mf < 2; ++mf) {
        #pragma unroll
        for (int nf = 0; nf < 2; ++nf) {
            #pragma unroll
            for (int j = 0; j < 4; ++j) {
                int hi = j >> 1;
                int co = mwbase + mf*16 + g + hi*8;
                int px = nw*16 + nf*8 + tg*2 + (j & 1);
                int rs = (px >= 56) ? 1 : 0;
                int row = 2*tile + rs;
                int col = px - rs*56;
                int loc = co*HWn + row*56 + col;
                float v = acc[mf][nf][j] + g_fb[bl*64 + co] + xb[loc];
                g_y[(size_t)bl*64*HWn + loc] = v;
                psum[mf][hi] += v;
                psq [mf][hi] += v*v;
            }
        }
    }
    #pragma unroll
    for (int mf = 0; mf < 2; ++mf)
        #pragma unroll
        for (int hi = 0; hi < 2; ++hi) {
            float s = psum[mf][hi], q = psq[mf][hi];
            s += __shfl_down_sync(0xffffffffu, s, 2, 4);
            s += __shfl_down_sync(0xffffffffu, s, 1, 4);
            q += __shfl_down_sync(0xffffffffu, q, 2, 4);
            q += __shfl_down_sync(0xffffffffu, q, 1, 4);
            if (tg == 0) {
                red_s[w][mf*16 + hi*8 + g] = s;
                red_q[w][mf*16 + hi*8 + g] = q;
            }
        }
    __syncthreads();
    if (tid < 64) {
        int co = tid;
        int mw2 = co >> 5; int rem = co & 31;
        int mf = rem >> 4; int g8 = rem & 15;
        int hi = g8 >> 3;  int g2 = g8 & 7;
        int idx = mf*16 + hi*8 + g2;
        float s = 0.f, q = 0.f;
        #pragma unroll
        for (int nw2 = 0; nw2 < 7; ++nw2) {
            s += red_s[nw2*2 + mw2][idx];
            q += red_q[nw2*2 + mw2][idx];
        }
        g_bnsum2[co*NBLK + bl*TILES + tile] = s;
        g_bnsq2 [co*NBLK + bl*TILES + tile] = q;
    }
}

// ============================================================================
// K4b: final BN statistics. 64 blocks, deterministic reduce over 1792.
// ============================================================================
__global__ __launch_bounds__(256) void k4b_stats() {
    int co  = blockIdx.x;
    int tid = threadIdx.x;
    float s = 0.f, q = 0.f;
    for (int i = tid; i < NBLK; i += 256) {
        s += g_bnsum2[co*NBLK + i];
        q += g_bnsq2 [co*NBLK + i];
    }
    #pragma unroll
    for (int off = 16; off > 0; off >>= 1) {
        s += __shfl_down_sync(0xffffffffu, s, off);
        q += __shfl_down_sync(0xffffffffu, q, off);
    }
    __shared__ float ws2[8], wq2[8];
    int wid = tid >> 5, lane = tid & 31;
    if (lane == 0) { ws2[wid] = s; wq2[wid] = q; }
    __syncthreads();
    if (tid == 0) {
        float S = 0.f, Q = 0.f;
        #pragma unroll
        for (int i = 0; i < 8; ++i) { S += ws2[i]; Q += wq2[i]; }
        const float invN = 1.0f / (float)(BLn * HWn);
        float mean = S * invN;
        float var  = Q * invN - mean*mean;
        g_mean[co]   = mean;
        g_invstd[co] = rsqrtf(var + 1e-5f);
    }
}

// ============================================================================
// K5: BN normalize + affine + SiLU -> d_out (unchanged)
// ============================================================================
__global__ __launch_bounds__(256) void k5_bnsilu(const float* __restrict__ gamma,
                                                 const float* __restrict__ beta,
                                                 float* __restrict__ out) {
    int i4 = blockIdx.x * 256 + threadIdx.x;
    int c = ((i4 * 4) / HWn) & 63;
    float4 y = ((const float4*)g_y)[i4];
    float m = g_mean[c], is = g_invstd[c] * gamma[c], bt = beta[c];
    float4 o;
    o.x = (y.x - m) * is + bt;
    o.y = (y.y - m) * is + bt;
    o.z = (y.z - m) * is + bt;
    o.w = (y.w - m) * is + bt;
    o.x = o.x / (1.0f + __expf(-o.x));
    o.y = o.y / (1.0f + __expf(-o.y));
    o.z = o.z / (1.0f + __expf(-o.z));
    o.w = o.w / (1.0f + __expf(-o.w));
    ((float4*)out)[i4] = o;
}

// ============================================================================
extern "C" void kernel_launch(void* const* d_in, const int* in_sizes, int n_in,
                              void* d_out, int out_size) {
    const float* x          = (const float*)d_in[0];
    const float* temporal_w = (const float*)d_in[1];
    const float* temporal_b = (const float*)d_in[2];
    const float* fc_w       = (const float*)d_in[3];
    const float* fc_b       = (const float*)d_in[4];
    const float* conv_w     = (const float*)d_in[5];
    const float* conv_b     = (const float*)d_in[6];
    const float* bn_gamma   = (const float*)d_in[7];
    const float* bn_beta    = (const float*)d_in[8];
    float* out = (float*)d_out;

    const int K1_SMEM = (2*56*33*2)*8 + 3*56*8 + (2*56*57)*4;   // 86016 B
    static int configured = 0;
    if (!configured) {
        cudaFuncSetAttribute(k1_dft2d, cudaFuncAttributeMaxDynamicSharedMemorySize, K1_SMEM);
        cudaFuncSetAttribute(k4t_conv, cudaFuncAttributeMaxDynamicSharedMemorySize, K4T_SMEM);
        configured = 1;
    }

    k0_aprep<<<72, 512>>>(conv_w);
    k1_dft2d<<<BCn*Ln/2, 224, K1_SMEM>>>(x);
    k2_ldft<<<BCn*4, 448>>>(x);
    k3_calib<<<BLn, 64>>>(temporal_w, temporal_b, fc_w, fc_b, conv_b);
    k4t_conv<<<dim3(TILES, BLn), 448, K4T_SMEM>>>(x, conv_w);
    k4b_stats<<<Cn, 256>>>();
    k5_bnsilu<<<NTOT/1024, 256>>>(bn_gamma, bn_beta, out);
}